// round 6
// baseline (speedup 1.0000x reference)
#include <cuda_runtime.h>
#include <cstdint>

typedef unsigned int u32;
typedef unsigned long long u64;

#define CS (65536L + 33554432L)   // per-component output stride (vn + sn)

// Swizzled tf32 A-operand images: id = comp*2 + kind (0: g^T for vn, 1: inv(g) for sn)
__device__ float g_Atf[6 * 16384];

// ---------------- helpers ---------------------------------------------------
__device__ __forceinline__ u32 smem_u32(const void* p) {
    u32 a;
    asm("{ .reg .u64 t; cvta.to.shared.u64 t, %1; cvt.u32.u64 %0, t; }" : "=r"(a) : "l"(p));
    return a;
}
__device__ __forceinline__ float to_tf32(float x) {
    float r;
    asm("cvt.rna.tf32.f32 %0, %1;" : "=f"(r) : "f"(x));
    return r;
}
__device__ __forceinline__ void ldsm_x4(u32& r0, u32& r1, u32& r2, u32& r3, u32 addr) {
    asm volatile("ldmatrix.sync.aligned.m8n8.x4.shared.b16 {%0,%1,%2,%3}, [%4];"
                 : "=r"(r0), "=r"(r1), "=r"(r2), "=r"(r3) : "r"(addr));
}
__device__ __forceinline__ void mma16808(float* c, const u32* a, const u32* b) {
    asm volatile("mma.sync.aligned.m16n8k8.row.col.f32.tf32.tf32.f32 "
                 "{%0,%1,%2,%3}, {%4,%5,%6,%7}, {%8,%9}, {%0,%1,%2,%3};"
                 : "+f"(c[0]), "+f"(c[1]), "+f"(c[2]), "+f"(c[3])
                 : "r"(a[0]), "r"(a[1]), "r"(a[2]), "r"(a[3]), "r"(b[0]), "r"(b[1]));
}
// swizzled [row][k] image offset: 512 B rows, 16 B chunks XOR (row & 7)
__device__ __forceinline__ u32 img_off(int m, int k) {
    return (u32)(m * 512 + (((k >> 2) ^ (m & 7)) << 4) + (k & 3) * 4);
}

// ---------------------------------------------------------------------------
// Blocks 0-2: Gauss-Jordan inversion (all register indices static).
// Writes the swizzled tf32 image of inv(g) (kind 1).
// Blocks 3-5: build the g^T image (kind 0).
// ---------------------------------------------------------------------------
__global__ void __launch_bounds__(256) invert_kernel(const float* __restrict__ G0,
                                                     const float* __restrict__ G1,
                                                     const float* __restrict__ G2)
{
    __shared__ float rowk[256];
    __shared__ float colk[128];
    const int b = blockIdx.x;
    const int tid = threadIdx.x;

    if (b >= 3) {   // prep: A = g^T, image id = comp*2
        const float* src = (b == 3) ? G0 : (b == 4 ? G1 : G2);
        const int id = (b - 3) * 2;
        for (int e = tid; e < 16384; e += 256) {
            const int m = e & 127, k = e >> 7;
            g_Atf[id * 16384 + (img_off(m, k) >> 2)] = to_tf32(src[k * 128 + m]);
        }
        return;
    }

    const float* G = b == 0 ? G0 : (b == 1 ? G1 : G2);
    const int cg = tid >> 5;        // warp id = column chunk
    const int c0 = cg * 32;
    const int rb = tid & 31;        // row within 32-row band

    float r[4][32];
#pragma unroll
    for (int a = 0; a < 4; a++) {
        const int i = rb + 32 * a;
#pragma unroll
        for (int c = 0; c < 32; c++) {
            const int gc = c0 + c;
            r[a][c] = (gc < 128) ? G[i * 128 + gc] : ((gc - 128 == i) ? 1.0f : 0.0f);
        }
    }

    for (int k = 0; k < 128; k++) {
        const int kl = k & 31, kh = k >> 5;
        if (rb == kl) {
#pragma unroll
            for (int a = 0; a < 4; a++) if (a == kh) {
#pragma unroll
                for (int c = 0; c < 32; c++) rowk[c0 + c] = r[a][c];
            }
        }
        if (cg == kh) {
#pragma unroll
            for (int t = 0; t < 32; t++) if (t == kl) {
#pragma unroll
                for (int a = 0; a < 4; a++) colk[rb + 32 * a] = r[a][t];
            }
        }
        __syncthreads();
        const float rinv = 1.0f / rowk[k];
        if (c0 + 31 >= k && c0 <= k + 128) {
            float rk[32];
#pragma unroll
            for (int c = 0; c < 32; c++) rk[c] = rowk[c0 + c];
#pragma unroll
            for (int a = 0; a < 4; a++) {
                const int i = rb + 32 * a;
                if (i == k) {
#pragma unroll
                    for (int c = 0; c < 32; c++) r[a][c] *= rinv;
                } else {
                    const float m = colk[i] * rinv;
#pragma unroll
                    for (int c = 0; c < 32; c++) r[a][c] -= m * rk[c];
                }
            }
        }
        __syncthreads();
    }

    if (cg >= 4) {
        const int id = b * 2 + 1;
#pragma unroll
        for (int a = 0; a < 4; a++) {
            const int i = rb + 32 * a;
#pragma unroll
            for (int c = 0; c < 32; c++)
                g_Atf[id * 16384 + (img_off(i, c0 - 128 + c) >> 2)] = to_tf32(r[a][c]);
        }
    }
}

// ---------------------------------------------------------------------------
// Main kernel: 148 persistent CTAs x 512 threads (16 warps). Tile = 128x128.
// tf32 mma.m16n8k8, fragments via ldmatrix.x4 (no trans), warp tile 32m x 32n.
// B tile: LDG fp32 (register staged, prefetch) -> cvt -> swizzled STS [n][k],
// double-buffered. A image resident in smem.
// ---------------------------------------------------------------------------
#define SM_A 0
#define SM_B 65536                       // 2 stages x 64 KB
#define SMEM_TOTAL (65536 * 3)           // 192 KB

__global__ void __launch_bounds__(512, 1) main_kernel(
    const float* __restrict__ v0, const float* __restrict__ v1, const float* __restrict__ v2,
    const float* __restrict__ s0, const float* __restrict__ s1, const float* __restrict__ s2,
    float* __restrict__ out)
{
    extern __shared__ char smem[];
    const u32 sb = smem_u32(smem);
    const int tid = threadIdx.x, wid = tid >> 5, lane = tid & 31;
    const int bid = blockIdx.x;

    int comp, t0, t1;
    bool sn;
    if (bid < 145) {
        sn = true;
        comp = bid % 3;
        const int nC = (comp == 0) ? 49 : 48;
        const int ci = bid / 3;
        t0 = (ci * 2048) / nC;
        t1 = ((ci + 1) * 2048) / nC;
    } else {
        sn = false;
        comp = bid - 145;
        t0 = 0;
        t1 = 4;
    }
    const int nt = t1 - t0;
    const long Ms = sn ? 262144L : 512L;
    const float* Bsrc = sn ? (comp == 0 ? s0 : comp == 1 ? s1 : s2)
                           : (comp == 0 ? v0 : comp == 1 ? v1 : v2);
    float* obase = out + (long)comp * CS + (sn ? 65536 : 0);
    const int imgid = comp * 2 + (sn ? 1 : 0);

    // copy pre-swizzled tf32 A image (64 KB)
    {
        const float4* Ai = (const float4*)(g_Atf + imgid * 16384);
#pragma unroll
        for (int q = 0; q < 8; q++)
            ((float4*)(smem + SM_A))[q * 512 + tid] = Ai[q * 512 + tid];
    }
    __syncthreads();

    const int wm = (wid & 3) * 32;       // warp row offset (m)
    const int wn = (wid >> 2) * 32;      // warp col offset (n)
    const int gidr = lane >> 2;          // groupID (0..7)
    const int gidc = lane & 3;           // threadID-in-group (0..3)

    // per-lane ldmatrix row bases
    const int xr = lane & 7;
    // A: matrices {m0..+8,c}, {m0+8..,c}, {m0..,c+1}, {m0+8..,c+1}
    const u32 arow0 = sb + SM_A + (u32)(wm + xr + ((lane >> 3) & 1) * 8) * 512;
    const u32 arow1 = arow0 + 16 * 512;
    const int acadd = lane >> 4;
    // B: matrices {n0..+8,c}, {n0..+8,c+1}, {n0+8..,c}, {n0+8..,c+1}
    const u32 brow0 = (u32)(wn + xr + (lane >> 4) * 8) * 512;
    const u32 brow1 = brow0 + 16 * 512;
    const int bcadd = (lane >> 3) & 1;

    float4 st[8];
    auto ldtile = [&](int t) {
        const float* src = Bsrc + (long)t * 128;
#pragma unroll
        for (int q = 0; q < 8; q++) {
            const int e = q * 512 + tid;          // chunk id: n = e&127, kc = e>>7
            const int n = e & 127;
            const float* pp = src + (long)((e >> 7) * 4) * Ms + n;
            st[q].x = pp[0];
            st[q].y = pp[Ms];
            st[q].z = pp[Ms * 2];
            st[q].w = pp[Ms * 3];
        }
    };
    ldtile(t0);

    for (int j = 0; j < nt; j++) {
        const int p = j & 1;

        // ---- convert + swizzled store: B[n][k] tf32 ----
        char* bp = smem + SM_B + p * 65536;
#pragma unroll
        for (int q = 0; q < 8; q++) {
            const int e = q * 512 + tid;
            const int n = e & 127, kc = e >> 7;
            float4 v = make_float4(to_tf32(st[q].x), to_tf32(st[q].y),
                                   to_tf32(st[q].z), to_tf32(st[q].w));
            *(float4*)(bp + n * 512 + ((kc ^ (n & 7)) << 4)) = v;
        }
        __syncthreads();

        // prefetch next tile during compute
        if (j + 1 < nt) ldtile(t0 + j + 1);

        // ---- compute: tf32 mma over K=128 (16 k-steps), ldmatrix fragments ----
        const u32 bB = sb + SM_B + p * 65536;

        float acc[2][4][4];
#pragma unroll
        for (int mi = 0; mi < 2; mi++)
#pragma unroll
            for (int ni = 0; ni < 4; ni++)
#pragma unroll
                for (int x = 0; x < 4; x++) acc[mi][ni][x] = 0.0f;

#pragma unroll
        for (int ks = 0; ks < 16; ks++) {
            const u32 ac = (u32)(((2 * ks + acadd) ^ xr) << 4);
            const u32 bc = (u32)(((2 * ks + bcadd) ^ xr) << 4);
            u32 av[2][4];
            ldsm_x4(av[0][0], av[0][1], av[0][2], av[0][3], arow0 + ac);
            ldsm_x4(av[1][0], av[1][1], av[1][2], av[1][3], arow1 + ac);
            u32 bv[4][2];
            ldsm_x4(bv[0][0], bv[0][1], bv[1][0], bv[1][1], bB + brow0 + bc);
            ldsm_x4(bv[2][0], bv[2][1], bv[3][0], bv[3][1], bB + brow1 + bc);
#pragma unroll
            for (int mi = 0; mi < 2; mi++)
#pragma unroll
                for (int ni = 0; ni < 4; ni++)
                    mma16808(acc[mi][ni], av[mi], bv[ni]);
        }

        // ---- epilogue: direct fp32 STG ----
        const long tcol = (long)(t0 + j) * 128;
#pragma unroll
        for (int mi = 0; mi < 2; mi++) {
            const int r = wm + mi * 16 + gidr;
            float* rp = obase + (long)r * Ms + tcol + wn + gidc * 2;
#pragma unroll
            for (int ni = 0; ni < 4; ni++) {
                *(float2*)(rp + ni * 8)          = make_float2(acc[mi][ni][0], acc[mi][ni][1]);
                *(float2*)(rp + ni * 8 + 8 * Ms) = make_float2(acc[mi][ni][2], acc[mi][ni][3]);
            }
        }
        // double buffer + next iteration's post-STS barrier orders buffer reuse
    }
}

// ---------------------------------------------------------------------------
// Inputs (metadata order): g0,g1,g2 (128x128), v0,v1,v2 (128x512),
// s0,s1,s2 (128x512x512). Output: [v0', s0', v1', s1', v2', s2'] flattened.
// ---------------------------------------------------------------------------
extern "C" void kernel_launch(void* const* d_in, const int* in_sizes, int n_in,
                              void* d_out, int out_size)
{
    const float* g0 = (const float*)d_in[0];
    const float* g1 = (const float*)d_in[1];
    const float* g2 = (const float*)d_in[2];
    const float* v0 = (const float*)d_in[3];
    const float* v1 = (const float*)d_in[4];
    const float* v2 = (const float*)d_in[5];
    const float* s0 = (const float*)d_in[6];
    const float* s1 = (const float*)d_in[7];
    const float* s2 = (const float*)d_in[8];
    float* out = (float*)d_out;

    cudaFuncSetAttribute(main_kernel, cudaFuncAttributeMaxDynamicSharedMemorySize, SMEM_TOTAL);

    invert_kernel<<<6, 256>>>(g0, g1, g2);   // blocks 0-2 invert, 3-5 prep g^T
    main_kernel<<<148, 512, SMEM_TOTAL>>>(v0, v1, v2, s0, s1, s2, out);
}

// round 7
// speedup vs baseline: 1.4680x; 1.4680x over previous
#include <cuda_runtime.h>
#include <cstdint>

typedef unsigned int u32;
typedef unsigned long long u64;

#define CS (65536L + 33554432L)   // per-component output stride (vn + sn)

// inv(g) stored transposed [k][m], fp32 (tf32-rounded at image build in main)
__device__ float g_invT[3 * 128 * 128];

// ---------------- helpers ---------------------------------------------------
__device__ __forceinline__ u32 smem_u32(const void* p) {
    u32 a;
    asm("{ .reg .u64 t; cvta.to.shared.u64 t, %1; cvt.u32.u64 %0, t; }" : "=r"(a) : "l"(p));
    return a;
}
__device__ __forceinline__ float to_tf32(float x) {
    float r;
    asm("cvt.rna.tf32.f32 %0, %1;" : "=f"(r) : "f"(x));
    return r;
}
__device__ __forceinline__ u32 lds32(u32 a) {
    u32 v;
    asm volatile("ld.shared.b32 %0, [%1];" : "=r"(v) : "r"(a));
    return v;
}
__device__ __forceinline__ void ldsm_x4(u32& r0, u32& r1, u32& r2, u32& r3, u32 addr) {
    asm volatile("ldmatrix.sync.aligned.m8n8.x4.shared.b16 {%0,%1,%2,%3}, [%4];"
                 : "=r"(r0), "=r"(r1), "=r"(r2), "=r"(r3) : "r"(addr));
}
__device__ __forceinline__ void mma16808(float* c, const u32* a, const u32* b) {
    asm volatile("mma.sync.aligned.m16n8k8.row.col.f32.tf32.tf32.f32 "
                 "{%0,%1,%2,%3}, {%4,%5,%6,%7}, {%8,%9}, {%0,%1,%2,%3};"
                 : "+f"(c[0]), "+f"(c[1]), "+f"(c[2]), "+f"(c[3])
                 : "r"(a[0]), "r"(a[1]), "r"(a[2]), "r"(a[3]), "r"(b[0]), "r"(b[1]));
}
__device__ __forceinline__ void cp16(u32 dst, const void* src) {
    asm volatile("cp.async.cg.shared.global [%0], [%1], 16;" :: "r"(dst), "l"(src));
}
// swizzled A image offset: row m, 512 B rows, 16 B chunks XOR (m & 7)
__device__ __forceinline__ u32 img_off(int m, int k) {
    return (u32)(m * 512 + (((k >> 2) ^ (m & 7)) << 4) + (k & 3) * 4);
}

// ---------------------------------------------------------------------------
// Gauss-Jordan inversion, one 128x128 per block, register-resident rows,
// all register indices static. ONE barrier per iteration (ping-pong bufs).
// Writes inv(g) transposed [k][m] to g_invT.
// ---------------------------------------------------------------------------
__global__ void __launch_bounds__(256) invert_kernel(const float* __restrict__ G0,
                                                     const float* __restrict__ G1,
                                                     const float* __restrict__ G2)
{
    __shared__ float rowk[2][256];
    __shared__ float colk[2][128];
    const int b = blockIdx.x;
    const int tid = threadIdx.x;
    const float* G = b == 0 ? G0 : (b == 1 ? G1 : G2);
    const int cg = tid >> 5;        // warp id = column chunk (warp-uniform gates)
    const int c0 = cg * 32;
    const int rb = tid & 31;

    float r[4][32];
#pragma unroll
    for (int a = 0; a < 4; a++) {
        const int i = rb + 32 * a;
#pragma unroll
        for (int c = 0; c < 32; c++) {
            const int gc = c0 + c;
            r[a][c] = (gc < 128) ? G[i * 128 + gc] : ((gc - 128 == i) ? 1.0f : 0.0f);
        }
    }

    for (int k = 0; k < 128; k++) {
        const int p = k & 1, kl = k & 31, kh = k >> 5;
        if (rb == kl) {
#pragma unroll
            for (int a = 0; a < 4; a++) if (a == kh) {
#pragma unroll
                for (int c = 0; c < 32; c++) rowk[p][c0 + c] = r[a][c];
            }
        }
        if (cg == kh) {
#pragma unroll
            for (int t = 0; t < 32; t++) if (t == kl) {
#pragma unroll
                for (int a = 0; a < 4; a++) colk[p][rb + 32 * a] = r[a][t];
            }
        }
        __syncthreads();
        const float rinv = 1.0f / rowk[p][k];
        if (c0 + 31 >= k && c0 <= k + 128) {
            float rk[32];
#pragma unroll
            for (int c = 0; c < 32; c++) rk[c] = rowk[p][c0 + c];
#pragma unroll
            for (int a = 0; a < 4; a++) {
                const int i = rb + 32 * a;
                if (i == k) {
#pragma unroll
                    for (int c = 0; c < 32; c++) r[a][c] *= rinv;
                } else {
                    const float m = colk[p][i] * rinv;
#pragma unroll
                    for (int c = 0; c < 32; c++) r[a][c] -= m * rk[c];
                }
            }
        }
    }

    if (cg >= 4) {
#pragma unroll
        for (int a = 0; a < 4; a++) {
            const int i = rb + 32 * a;
#pragma unroll
            for (int c = 0; c < 32; c++)
                g_invT[b * 16384 + (c0 - 128 + c) * 128 + i] = r[a][c];
        }
    }
}

// ---------------------------------------------------------------------------
// Main kernel: 148 persistent CTAs x 256 threads (8 warps, 64m x 32n warp
// tiles). Tile = 128x128 output. A (tf32, rna) resident in smem, swizzled
// for ldmatrix. B streamed with cp.async raw fp32 into native [k][n] layout
// (chunk-XOR swizzled), fragments via conflict-free LDS.32; HMMA consumes
// tf32 bits (truncation on B only). Double-buffered, 2-deep cp.async pipe.
// ---------------------------------------------------------------------------
#define SM_A 0
#define SM_B 65536                       // 2 stages x 64 KB
#define SMEM_TOTAL (65536 * 3)           // 192 KB

__global__ void __launch_bounds__(256, 1) main_kernel(
    const float* __restrict__ g0, const float* __restrict__ g1, const float* __restrict__ g2,
    const float* __restrict__ v0, const float* __restrict__ v1, const float* __restrict__ v2,
    const float* __restrict__ s0, const float* __restrict__ s1, const float* __restrict__ s2,
    float* __restrict__ out)
{
    extern __shared__ char smem[];
    const u32 sb = smem_u32(smem);
    const int tid = threadIdx.x, wid = tid >> 5, lane = tid & 31;
    const int bid = blockIdx.x;

    int comp, t0, t1;
    bool sn;
    if (bid < 145) {
        sn = true;
        comp = bid % 3;
        const int nC = (comp == 0) ? 49 : 48;
        const int ci = bid / 3;
        t0 = (ci * 2048) / nC;
        t1 = ((ci + 1) * 2048) / nC;
    } else {
        sn = false;
        comp = bid - 145;
        t0 = 0;
        t1 = 4;
    }
    const int nt = t1 - t0;
    const long Ms = sn ? 262144L : 512L;
    const float* Bsrc = sn ? (comp == 0 ? s0 : comp == 1 ? s1 : s2)
                           : (comp == 0 ? v0 : comp == 1 ? v1 : v2);
    float* obase = out + (long)comp * CS + (sn ? 65536 : 0);

    // ---- cp.async pipeline: issue tile t into buffer p ----
    auto cpissue = [&](int t, int p) {
        const float* src = Bsrc + (long)t * 128;
        const u32 bdst = sb + SM_B + p * 65536;
#pragma unroll
        for (int q = 0; q < 16; q++) {
            const int e = q * 256 + tid;
            const int k = e >> 5, c = e & 31;
            cp16(bdst + k * 512 + ((c ^ ((k & 3) << 1)) << 4),
                 src + (long)k * Ms + c * 4);
        }
        asm volatile("cp.async.commit_group;" ::: "memory");
    };

    // get DRAM going before building A image
    cpissue(t0, 0);
    if (nt > 1) cpissue(t0 + 1, 1);

    // ---- build swizzled tf32 A image (A[m][k] = src[k*128+m]) ----
    {
        const float* Gc = comp == 0 ? g0 : (comp == 1 ? g1 : g2);
        const float* asrc = sn ? (g_invT + comp * 16384) : Gc;
        for (int e = tid; e < 16384; e += 256) {
            const int m = e & 127, k = e >> 7;
            *(float*)(smem + SM_A + img_off(m, k)) = to_tf32(asrc[k * 128 + m]);
        }
    }

    const int wm = (wid & 1) * 64;       // warp row offset (m), WM=64
    const int wn = (wid >> 1) * 32;      // warp col offset (n), WN=32
    const int gidr = lane >> 2;          // 0..7
    const int gidc = lane & 3;           // 0..3
    const int xr = lane & 7;
    const int hi8 = (lane >> 3) & 1;
    const int q16 = lane >> 4;

    // A ldmatrix per-lane row bases (4 mi-tiles of 16 rows)
    u32 arow[4];
#pragma unroll
    for (int mi = 0; mi < 4; mi++)
        arow[mi] = sb + SM_A + (u32)(wm + mi * 16 + xr + hi8 * 8) * 512;

    // B per-lane chunk bases (4 ni-tiles of 8 cols)
    u32 cb[4];
#pragma unroll
    for (int ni = 0; ni < 4; ni++) {
        const int n = wn + ni * 8 + gidr;
        cb[ni] = (u32)(((((n >> 2) ^ (gidc << 1)) & 31) << 4) + (n & 3) * 4);
    }

    for (int j = 0; j < nt; j++) {
        const int p = j & 1;

        if (j + 1 < nt) asm volatile("cp.async.wait_group 1;" ::: "memory");
        else            asm volatile("cp.async.wait_group 0;" ::: "memory");
        __syncthreads();

        const u32 bB = sb + SM_B + p * 65536;

        float acc[4][4][4];
#pragma unroll
        for (int mi = 0; mi < 4; mi++)
#pragma unroll
            for (int ni = 0; ni < 4; ni++)
#pragma unroll
                for (int x = 0; x < 4; x++) acc[mi][ni][x] = 0.0f;

#pragma unroll
        for (int ks = 0; ks < 16; ks++) {
            const u32 acol = (u32)(((2 * ks + q16) ^ xr) << 4);
            u32 av[4][4];
#pragma unroll
            for (int mi = 0; mi < 4; mi++)
                ldsm_x4(av[mi][0], av[mi][1], av[mi][2], av[mi][3], arow[mi] + acol);
            const u32 brow = bB + (u32)(8 * ks + gidc) * 512;
            u32 bv[4][2];
#pragma unroll
            for (int ni = 0; ni < 4; ni++) {
                bv[ni][0] = lds32(brow + cb[ni]);
                bv[ni][1] = lds32(brow + 2048 + cb[ni]);
            }
#pragma unroll
            for (int mi = 0; mi < 4; mi++)
#pragma unroll
                for (int ni = 0; ni < 4; ni++)
                    mma16808(acc[mi][ni], av[mi], bv[ni]);
        }

        // ---- epilogue: direct fp32 STG ----
        const long tcol = (long)(t0 + j) * 128;
#pragma unroll
        for (int mi = 0; mi < 4; mi++) {
            const int r = wm + mi * 16 + gidr;
            float* rp = obase + (long)r * Ms + tcol + wn + gidc * 2;
#pragma unroll
            for (int ni = 0; ni < 4; ni++) {
                *(float2*)(rp + ni * 8)          = make_float2(acc[mi][ni][0], acc[mi][ni][1]);
                *(float2*)(rp + ni * 8 + 8 * Ms) = make_float2(acc[mi][ni][2], acc[mi][ni][3]);
            }
        }

        __syncthreads();                 // all warps done reading buf p
        if (j + 2 < nt) cpissue(t0 + j + 2, p);
    }
}

// ---------------------------------------------------------------------------
// Inputs (metadata order): g0,g1,g2 (128x128), v0,v1,v2 (128x512),
// s0,s1,s2 (128x512x512). Output: [v0', s0', v1', s1', v2', s2'] flattened.
// ---------------------------------------------------------------------------
extern "C" void kernel_launch(void* const* d_in, const int* in_sizes, int n_in,
                              void* d_out, int out_size)
{
    const float* g0 = (const float*)d_in[0];
    const float* g1 = (const float*)d_in[1];
    const float* g2 = (const float*)d_in[2];
    const float* v0 = (const float*)d_in[3];
    const float* v1 = (const float*)d_in[4];
    const float* v2 = (const float*)d_in[5];
    const float* s0 = (const float*)d_in[6];
    const float* s1 = (const float*)d_in[7];
    const float* s2 = (const float*)d_in[8];
    float* out = (float*)d_out;

    cudaFuncSetAttribute(main_kernel, cudaFuncAttributeMaxDynamicSharedMemorySize, SMEM_TOTAL);

    invert_kernel<<<3, 256>>>(g0, g1, g2);
    main_kernel<<<148, 256, SMEM_TOTAL>>>(g0, g1, g2, v0, v1, v2, s0, s1, s2, out);
}